// round 1
// baseline (speedup 1.0000x reference)
#include <cuda_runtime.h>
#include <stdint.h>

#define T_STEPS 2000
#define BATCH   1024
#define NS      16
#define NA      4
#define STRIDE_T (BATCH * NS)

// LIF step, bit-exact with the reference fp32 sequence:
//   v = v + (x - (v - 0)) / TAU   with TAU == 1.0f in fp32  -> v = v + (x - v)
//   spike = heaviside(v - 1)  (1 at exactly threshold)
//   hard reset: v = (1 - s) * v  ==  (s ? 0 : v)
__device__ __forceinline__ float lif_step(float& v, float x) {
    float dv = x - v;        // FADD (no FMA possible: no multiply)
    v = v + dv;              // FADD
    bool fire = (v >= 1.0f);
    float s = fire ? 1.0f : 0.0f;
    v = fire ? 0.0f : v;
    return s;
}

__global__ __launch_bounds__(128, 8)
void bg_actor_kernel(const float* __restrict__ pfc,
                     const float* __restrict__ w_pfc_d1,
                     const float* __restrict__ w_pfc_d2,
                     float* __restrict__ out, int out_size)
{
    // byte-pair LUTs for the two 16x4 dot products:
    // lut[0]=d1 low byte, lut[1]=d1 high byte, lut[2]=d2 low, lut[3]=d2 high
    __shared__ float lut[4][256][4];   // 16 KB

    const int tid = threadIdx.x;
    for (int e = tid; e < 4 * 256; e += blockDim.x) {
        const int tab = e >> 8;
        const int m   = e & 255;
        const float* w = (tab < 2) ? w_pfc_d1 : w_pfc_d2;
        const int ibase = (tab & 1) ? 8 : 0;
        #pragma unroll
        for (int j = 0; j < NA; j++) {
            float acc = 0.0f;
            #pragma unroll
            for (int i = 0; i < 8; i++)
                if ((m >> i) & 1) acc += w[(ibase + i) * NA + j];
            lut[tab][m][j] = acc;
        }
    }
    __syncthreads();

    const int lane = tid & 31;
    const int gwarp = (blockIdx.x * blockDim.x + tid) >> 5;   // 0..511
    const int grp  = lane >> 4;          // which batch within warp
    const int li   = lane & 15;          // pfc neuron index
    const int b    = gwarp * 2 + grp;    // batch element 0..1023
    const int j    = lane & 3;           // downstream action channel

    // pathway weights, computed in the same fp32 op order as the reference
    const float w1j = (j == 0) ? 0.2f : (j == 1) ? 0.12f : (j == 2) ? 0.07f : 0.03f;
    const float w2j = (j == 0) ? 0.03f : (j == 1) ? 0.07f : (j == 2) ? 0.12f : 0.2f;
    const float W_D1_GPI   = (-1.0f * w1j) * 5.0f;
    const float W_D2_GPE   = (-1.0f * w1j) * 5.0f;
    const float W_GPE_STN  = (-0.8f * w1j) * 5.0f;
    const float W_STN_GPI  = (1.2f  * w1j) * 5.0f;
    const float W_GPI_THAL = (-1.0f * w2j) * 5.0f;
    const float W_THAL_PMC = (1.0f  * w1j) * 5.0f;

    float v_pfc = 0.0f, v_d1 = 0.0f, v_d2 = 0.0f, v_gpe = 0.0f,
          v_stn = 0.0f, v_gpi = 0.0f, v_thal = 0.0f, v_pmc = 0.0f;
    float acc = 0.0f;

    const float* p = pfc + b * NS + li;

    float bufA[8], bufB[8];
    #pragma unroll
    for (int k = 0; k < 8; k++) bufA[k] = p[k * STRIDE_T];
    p += 8 * STRIDE_T;

    const unsigned full = 0xffffffffu;
    const int shift = grp * 16;

    #define DO_STEP(xv)                                                        \
    {                                                                          \
        float s_pfc = lif_step(v_pfc, (xv));                                   \
        unsigned bal = __ballot_sync(full, s_pfc > 0.5f);                      \
        unsigned m   = (bal >> shift) & 0xFFFFu;                               \
        unsigned mlo = m & 255u, mhi = m >> 8;                                 \
        float d1c = lut[0][mlo][j] + lut[1][mhi][j];                           \
        float d2c = lut[2][mlo][j] + lut[3][mhi][j];                           \
        float s_d1 = lif_step(v_d1, d1c);                                      \
        float s_d2 = lif_step(v_d2, d2c);                                      \
        float s_gpe = lif_step(v_gpe, s_d2 * W_D2_GPE + 1.5f);                 \
        float s_stn = lif_step(v_stn, s_gpe * W_GPE_STN + 1.8f);               \
        float gd = s_d1 * W_D1_GPI;                                            \
        float s_gpi = lif_step(v_gpi, (gd + s_stn * W_STN_GPI) + 1.5f);        \
        float s_thal = lif_step(v_thal, s_gpi * W_GPI_THAL + 1.2f);            \
        float s_pmc = lif_step(v_pmc, s_thal * W_THAL_PMC + 0.5f);             \
        acc += s_pmc;                                                          \
    }

    for (int t0 = 0; t0 < T_STEPS; t0 += 16) {
        #pragma unroll
        for (int k = 0; k < 8; k++) bufB[k] = p[k * STRIDE_T];
        p += 8 * STRIDE_T;

        #pragma unroll
        for (int k = 0; k < 8; k++) DO_STEP(bufA[k]);

        if (t0 + 16 < T_STEPS) {
            #pragma unroll
            for (int k = 0; k < 8; k++) bufA[k] = p[k * STRIDE_T];
            p += 8 * STRIDE_T;
        }

        #pragma unroll
        for (int k = 0; k < 8; k++) DO_STEP(bufB[k]);
    }
    #undef DO_STEP

    // gather the 4 accumulators of this batch's group (lanes grp*16 + 0..3)
    float a0 = __shfl_sync(full, acc, shift + 0);
    float a1 = __shfl_sync(full, acc, shift + 1);
    float a2 = __shfl_sync(full, acc, shift + 2);
    float a3 = __shfl_sync(full, acc, shift + 3);

    int best = 0; float bv = a0;
    if (a1 > bv) { bv = a1; best = 1; }
    if (a2 > bv) { bv = a2; best = 2; }
    if (a3 > bv) { bv = a3; best = 3; }

    if (out_size == BATCH * (1 + NA)) {
        // float32 layout: [action (B)] then [pmc totals (B,4)]
        if (li < 4) out[BATCH + b * NA + j] = acc;
        if (li == 0) out[b] = (float)best;
    } else if (out_size == BATCH * NA) {
        if (li < 4) out[b * NA + j] = acc;
    } else if (out_size == BATCH) {
        if (li == 0) ((int*)out)[b] = best;
    } else {
        // fallback: write pmc totals at start, action after if room
        if (li < 4 && b * NA + j < out_size) out[b * NA + j] = acc;
        if (li == 0 && BATCH * NA + b < out_size) out[BATCH * NA + b] = (float)best;
    }
}

extern "C" void kernel_launch(void* const* d_in, const int* in_sizes, int n_in,
                              void* d_out, int out_size) {
    const float* pfc = (const float*)d_in[0];   // [2000, 1024, 16] f32
    const float* w1  = (const float*)d_in[1];   // [16, 4] f32
    const float* w2  = (const float*)d_in[2];   // [16, 4] f32
    bg_actor_kernel<<<128, 128>>>(pfc, w1, w2, (float*)d_out, out_size);
}

// round 3
// speedup vs baseline: 1.4678x; 1.4678x over previous
#include <cuda_runtime.h>
#include <stdint.h>

#define T_STEPS 2000
#define BATCH   1024
#define NS      16
#define NA      4
#define STRIDE_T (BATCH * NS)

// LIF step, bit-exact fp32 sequence (TAU == 1.0f in fp32):
//   v = v + (x - v); spike = (v >= 1); hard reset v = spike ? 0 : v
__device__ __forceinline__ bool lif_b(float& v, float x) {
    float dv = x - v;
    v = v + dv;
    bool fire = (v >= 1.0f);
    v = fire ? 0.0f : v;
    return fire;
}

__global__ __launch_bounds__(128, 4)
void bg_actor_kernel(const float* __restrict__ pfc,
                     const float* __restrict__ w_pfc_d1,
                     const float* __restrict__ w_pfc_d2,
                     float* __restrict__ out, int out_size)
{
    // byte-pair LUTs, packed: lutA[m][j] = (d1 low-byte sum, d2 low-byte sum)
    //                         lutB[m][j] = (d1 high-byte sum, d2 high-byte sum)
    __shared__ float2 lutA[256][NA];
    __shared__ float2 lutB[256][NA];

    const int tid = threadIdx.x;
    for (int e = tid; e < 512; e += blockDim.x) {
        const int hi = e >> 8;
        const int m  = e & 255;
        const int ibase = hi ? 8 : 0;
        #pragma unroll
        for (int j = 0; j < NA; j++) {
            float a1 = 0.0f, a2 = 0.0f;
            #pragma unroll
            for (int i = 0; i < 8; i++)
                if ((m >> i) & 1) {
                    a1 += w_pfc_d1[(ibase + i) * NA + j];
                    a2 += w_pfc_d2[(ibase + i) * NA + j];
                }
            if (hi) lutB[m][j] = make_float2(a1, a2);
            else    lutA[m][j] = make_float2(a1, a2);
        }
    }
    __syncthreads();

    const int lane  = tid & 31;
    const int gwarp = (blockIdx.x * blockDim.x + tid) >> 5;   // 0..511
    const int grp   = lane >> 4;
    const int li    = lane & 15;
    const int b     = gwarp * 2 + grp;
    const int j     = lane & 3;
    const int shift = grp * 16;
    const unsigned full = 0xffffffffu;

    const float w1j = (j == 0) ? 0.2f : (j == 1) ? 0.12f : (j == 2) ? 0.07f : 0.03f;
    const float w2j = (j == 0) ? 0.03f : (j == 1) ? 0.07f : (j == 2) ? 0.12f : 0.2f;
    const float W_D1_GPI   = (-1.0f * w1j) * 5.0f;
    const float W_D2_GPE   = (-1.0f * w1j) * 5.0f;
    const float W_GPE_STN  = (-0.8f * w1j) * 5.0f;
    const float W_STN_GPI  = (1.2f  * w1j) * 5.0f;
    const float W_GPI_THAL = (-1.0f * w2j) * 5.0f;
    const float W_THAL_PMC = (1.0f  * w1j) * 5.0f;
    // spike-on currents: fl(fl(1*W)+base) == fl(W+base)
    const float C_GPE_ON  = W_D2_GPE   + 1.5f;
    const float C_STN_ON  = W_GPE_STN  + 1.8f;
    const float C_THAL_ON = W_GPI_THAL + 1.2f;
    const float C_PMC_ON  = W_THAL_PMC + 0.5f;

    float v_pfc = 0.0f, v_d1 = 0.0f, v_d2 = 0.0f, v_gpe = 0.0f,
          v_stn = 0.0f, v_gpi = 0.0f, v_thal = 0.0f, v_pmc = 0.0f;
    int acc_i = 0;

    // pipeline registers (stage L processes timestep t - L)
    bool s_pfc_b = false, s_d2_b = false, s_gpe_b = false,
         s_stn_b = false, s_gpi_b = false, s_thal_b = false;
    bool sd1q0 = false, sd1q1 = false, sd1q2 = false;  // 3-deep delay for s_d1 -> gpi
    unsigned m_reg = 0;
    float d1c = 0.0f, d2c = 0.0f;

    // One skewed pipeline iteration. Stages written in reverse pipeline order so
    // every stage reads the previous iteration's value before it is overwritten.
    #define STEP(xv, EN_PFC, EN_BAL, EN_LDS, EN_D12, EN_GPE, EN_STN, EN_GPI, EN_THAL, EN_PMC) \
    {                                                                                          \
        if (EN_PMC)  { float x = s_thal_b ? C_PMC_ON : 0.5f;                                   \
                       acc_i += lif_b(v_pmc, x) ? 1 : 0; }                                     \
        if (EN_THAL) { float x = s_gpi_b ? C_THAL_ON : 1.2f;                                   \
                       s_thal_b = lif_b(v_thal, x); }                                          \
        if (EN_GPI)  { float ga = sd1q2 ? W_D1_GPI : 0.0f;                                     \
                       float gb = s_stn_b ? W_STN_GPI : 0.0f;                                  \
                       float x = (ga + gb) + 1.5f;                                             \
                       s_gpi_b = lif_b(v_gpi, x); }                                            \
        if (EN_STN)  { float x = s_gpe_b ? C_STN_ON : 1.8f;                                    \
                       s_stn_b = lif_b(v_stn, x); }                                            \
        if (EN_GPE)  { float x = s_d2_b ? C_GPE_ON : 1.5f;                                     \
                       s_gpe_b = lif_b(v_gpe, x); }                                            \
        if (EN_D12)  { bool nd1 = lif_b(v_d1, d1c);                                            \
                       s_d2_b = lif_b(v_d2, d2c);                                              \
                       sd1q2 = sd1q1; sd1q1 = sd1q0; sd1q0 = nd1; }                            \
        if (EN_LDS)  { unsigned mlo = m_reg & 255u, mhi = m_reg >> 8;                          \
                       float2 A  = lutA[mlo][j];                                               \
                       float2 Bv = lutB[mhi][j];                                               \
                       d1c = A.x + Bv.x;                                                       \
                       d2c = A.y + Bv.y; }                                                     \
        if (EN_BAL)  { unsigned bal = __ballot_sync(full, s_pfc_b);                            \
                       m_reg = (bal >> shift) & 0xFFFFu; }                                     \
        if (EN_PFC)  { s_pfc_b = lif_b(v_pfc, (xv)); }                                         \
    }
    #define STEP_F(xv) STEP(xv, 1,1,1,1,1,1,1,1,1)

    const float* p = pfc + b * NS + li;
    float bufA[8], bufB[8];

    #pragma unroll
    for (int k = 0; k < 8; k++) bufA[k] = p[k * STRIDE_T];
    p += 8 * STRIDE_T;
    #pragma unroll
    for (int k = 0; k < 8; k++) bufB[k] = p[k * STRIDE_T];
    p += 8 * STRIDE_T;

    // ---- prologue: pipeline fill, t = 0..7 (compile-time stage enables) ----
    STEP(bufA[0], 1,0,0,0,0,0,0,0,0);
    STEP(bufA[1], 1,1,0,0,0,0,0,0,0);
    STEP(bufA[2], 1,1,1,0,0,0,0,0,0);
    STEP(bufA[3], 1,1,1,1,0,0,0,0,0);
    STEP(bufA[4], 1,1,1,1,1,0,0,0,0);
    STEP(bufA[5], 1,1,1,1,1,1,0,0,0);
    STEP(bufA[6], 1,1,1,1,1,1,1,0,0);
    STEP(bufA[7], 1,1,1,1,1,1,1,1,0);

    // ---- main: chunks 1..248 (pairs), t = 8..1991 ----
    #pragma unroll 1
    for (int c = 1; c <= 247; c += 2) {
        #pragma unroll
        for (int k = 0; k < 8; k++) bufA[k] = p[k * STRIDE_T];
        p += 8 * STRIDE_T;
        #pragma unroll
        for (int k = 0; k < 8; k++) STEP_F(bufB[k]);
        #pragma unroll
        for (int k = 0; k < 8; k++) bufB[k] = p[k * STRIDE_T];
        p += 8 * STRIDE_T;
        #pragma unroll
        for (int k = 0; k < 8; k++) STEP_F(bufA[k]);
    }
    // ---- chunk 249: t = 1992..1999 (already prefetched into bufB) ----
    #pragma unroll
    for (int k = 0; k < 8; k++) STEP_F(bufB[k]);

    // ---- epilogue: pipeline drain, t = 2000..2007 (no pfc stage / no loads) ----
    #pragma unroll
    for (int k = 0; k < 8; k++) STEP(0.0f, 0,1,1,1,1,1,1,1,1);

    #undef STEP_F
    #undef STEP

    float acc = (float)acc_i;

    // gather the 4 accumulators of this batch's group (lanes grp*16 + 0..3)
    float a0 = __shfl_sync(full, acc, shift + 0);
    float a1 = __shfl_sync(full, acc, shift + 1);
    float a2 = __shfl_sync(full, acc, shift + 2);
    float a3 = __shfl_sync(full, acc, shift + 3);

    int best = 0; float bv = a0;
    if (a1 > bv) { bv = a1; best = 1; }
    if (a2 > bv) { bv = a2; best = 2; }
    if (a3 > bv) { bv = a3; best = 3; }

    if (out_size == BATCH * (1 + NA)) {
        if (li < 4) out[BATCH + b * NA + j] = acc;
        if (li == 0) out[b] = (float)best;
    } else if (out_size == BATCH * NA) {
        if (li < 4) out[b * NA + j] = acc;
    } else if (out_size == BATCH) {
        if (li == 0) ((int*)out)[b] = best;
    } else {
        if (li < 4 && b * NA + j < out_size) out[b * NA + j] = acc;
        if (li == 0 && BATCH * NA + b < out_size) out[BATCH * NA + b] = (float)best;
    }
}

extern "C" void kernel_launch(void* const* d_in, const int* in_sizes, int n_in,
                              void* d_out, int out_size) {
    const float* pfc = (const float*)d_in[0];   // [2000, 1024, 16] f32
    const float* w1  = (const float*)d_in[1];   // [16, 4] f32
    const float* w2  = (const float*)d_in[2];   // [16, 4] f32
    bg_actor_kernel<<<128, 128>>>(pfc, w1, w2, (float*)d_out, out_size);
}

// round 4
// speedup vs baseline: 2.4705x; 1.6832x over previous
#include <cuda_runtime.h>
#include <stdint.h>

#define T_STEPS 2000
#define BATCH   1024
#define NS      16
#define NA      4
#define STRIDE_T (BATCH * NS)

#define C_CHUNKS 10
#define K_CHUNK  200     // payload timesteps per chunk (C*K = T)
#define HALO     48      // warm-up steps (multiple of 8); chunk 0 has none

__device__ int g_acc[BATCH * NA];   // partial PMC spike counts

// LIF step, bit-exact fp32 sequence (TAU == 1.0f in fp32):
//   v = v + (x - v); spike = (v >= 1); hard reset v = spike ? 0 : v
__device__ __forceinline__ bool lif_b(float& v, float x) {
    float dv = x - v;
    v = v + dv;
    bool fire = (v >= 1.0f);
    v = fire ? 0.0f : v;
    return fire;
}

__global__ void zero_kernel() {
    int i = blockIdx.x * blockDim.x + threadIdx.x;
    if (i < BATCH * NA) g_acc[i] = 0;
}

__global__ __launch_bounds__(128, 9)
void bg_chunk_kernel(const float* __restrict__ pfc,
                     const float* __restrict__ w_pfc_d1,
                     const float* __restrict__ w_pfc_d2)
{
    __shared__ float2 lutA[256][NA];
    __shared__ float2 lutB[256][NA];

    const int tid = threadIdx.x;
    for (int e = tid; e < 512; e += blockDim.x) {
        const int hi = e >> 8;
        const int m  = e & 255;
        const int ibase = hi ? 8 : 0;
        #pragma unroll
        for (int j = 0; j < NA; j++) {
            float a1 = 0.0f, a2 = 0.0f;
            #pragma unroll
            for (int i = 0; i < 8; i++)
                if ((m >> i) & 1) {
                    a1 += w_pfc_d1[(ibase + i) * NA + j];
                    a2 += w_pfc_d2[(ibase + i) * NA + j];
                }
            if (hi) lutB[m][j] = make_float2(a1, a2);
            else    lutA[m][j] = make_float2(a1, a2);
        }
    }
    __syncthreads();

    const int lane  = tid & 31;
    const int g     = blockIdx.x * 4 + (tid >> 5);  // global warp 0..5119
    const int pair  = g / C_CHUNKS;                 // batch pair 0..511
    const int chunk = g - pair * C_CHUNKS;          // 0..9
    const int grp   = lane >> 4;
    const int li    = lane & 15;
    const int b     = pair * 2 + grp;
    const int j     = lane & 3;
    const int shift = grp * 16;
    const unsigned full = 0xffffffffu;

    const float w1j = (j == 0) ? 0.2f : (j == 1) ? 0.12f : (j == 2) ? 0.07f : 0.03f;
    const float w2j = (j == 0) ? 0.03f : (j == 1) ? 0.07f : (j == 2) ? 0.12f : 0.2f;
    const float W_D1_GPI   = (-1.0f * w1j) * 5.0f;
    const float W_D2_GPE   = (-1.0f * w1j) * 5.0f;
    const float W_GPE_STN  = (-0.8f * w1j) * 5.0f;
    const float W_STN_GPI  = (1.2f  * w1j) * 5.0f;
    const float W_GPI_THAL = (-1.0f * w2j) * 5.0f;
    const float W_THAL_PMC = (1.0f  * w1j) * 5.0f;
    const float C_GPE_ON  = W_D2_GPE   + 1.5f;
    const float C_STN_ON  = W_GPE_STN  + 1.8f;
    const float C_THAL_ON = W_GPI_THAL + 1.2f;
    const float C_PMC_ON  = W_THAL_PMC + 0.5f;

    // chunk geometry
    const int t0     = chunk * K_CHUNK - (chunk ? HALO : 0);
    const int npair  = chunk ? (HALO + K_CHUNK - 8) / 16 : (K_CHUNK - 8) / 16; // 15 / 12
    const int bsnap  = chunk ? 3 : 0;   // pair index whose first 8-group starts at iter 56 (or 8)

    float v_pfc = 0.0f, v_d1 = 0.0f, v_d2 = 0.0f, v_gpe = 0.0f,
          v_stn = 0.0f, v_gpi = 0.0f, v_thal = 0.0f, v_pmc = 0.0f;
    int acc_i = 0, base_acc = 0;

    bool s_pfc_b = false, s_d2_b = false, s_gpe_b = false,
         s_stn_b = false, s_gpi_b = false, s_thal_b = false;
    bool sd1q0 = false, sd1q1 = false, sd1q2 = false;
    unsigned m_reg = 0;
    float d1c = 0.0f, d2c = 0.0f;

    #define STEP(xv, EN_PFC, EN_BAL, EN_LDS, EN_D12, EN_GPE, EN_STN, EN_GPI, EN_THAL, EN_PMC) \
    {                                                                                          \
        if (EN_PMC)  { float x = s_thal_b ? C_PMC_ON : 0.5f;                                   \
                       acc_i += lif_b(v_pmc, x) ? 1 : 0; }                                     \
        if (EN_THAL) { float x = s_gpi_b ? C_THAL_ON : 1.2f;                                   \
                       s_thal_b = lif_b(v_thal, x); }                                          \
        if (EN_GPI)  { float ga = sd1q2 ? W_D1_GPI : 0.0f;                                     \
                       float gb = s_stn_b ? W_STN_GPI : 0.0f;                                  \
                       float x = (ga + gb) + 1.5f;                                             \
                       s_gpi_b = lif_b(v_gpi, x); }                                            \
        if (EN_STN)  { float x = s_gpe_b ? C_STN_ON : 1.8f;                                    \
                       s_stn_b = lif_b(v_stn, x); }                                            \
        if (EN_GPE)  { float x = s_d2_b ? C_GPE_ON : 1.5f;                                     \
                       s_gpe_b = lif_b(v_gpe, x); }                                            \
        if (EN_D12)  { bool nd1 = lif_b(v_d1, d1c);                                            \
                       s_d2_b = lif_b(v_d2, d2c);                                              \
                       sd1q2 = sd1q1; sd1q1 = sd1q0; sd1q0 = nd1; }                            \
        if (EN_LDS)  { unsigned mlo = m_reg & 255u, mhi = m_reg >> 8;                          \
                       float2 A  = lutA[mlo][j];                                               \
                       float2 Bv = lutB[mhi][j];                                               \
                       d1c = A.x + Bv.x;                                                       \
                       d2c = A.y + Bv.y; }                                                     \
        if (EN_BAL)  { unsigned bal = __ballot_sync(full, s_pfc_b);                            \
                       m_reg = (bal >> shift) & 0xFFFFu; }                                     \
        if (EN_PFC)  { s_pfc_b = lif_b(v_pfc, (xv)); }                                         \
    }
    #define STEP_F(xv) STEP(xv, 1,1,1,1,1,1,1,1,1)

    const float* p = pfc + (size_t)t0 * STRIDE_T + b * NS + li;
    float bufA[8], bufB[8];

    #pragma unroll
    for (int k = 0; k < 8; k++) bufA[k] = p[k * STRIDE_T];
    p += 8 * STRIDE_T;
    #pragma unroll
    for (int k = 0; k < 8; k++) bufB[k] = p[k * STRIDE_T];
    p += 8 * STRIDE_T;

    // ---- pipeline fill: local t = 0..7 ----
    STEP(bufA[0], 1,0,0,0,0,0,0,0,0);
    STEP(bufA[1], 1,1,0,0,0,0,0,0,0);
    STEP(bufA[2], 1,1,1,0,0,0,0,0,0);
    STEP(bufA[3], 1,1,1,1,0,0,0,0,0);
    STEP(bufA[4], 1,1,1,1,1,0,0,0,0);
    STEP(bufA[5], 1,1,1,1,1,1,0,0,0);
    STEP(bufA[6], 1,1,1,1,1,1,1,0,0);
    STEP(bufA[7], 1,1,1,1,1,1,1,1,0);

    // ---- main: npair pairs of 8-step groups, local t = 8..nsteps-1 ----
    #pragma unroll 1
    for (int i = 0; i < npair; i++) {
        base_acc = (i == bsnap) ? acc_i : base_acc;   // halo/payload boundary snapshot
        #pragma unroll
        for (int k = 0; k < 8; k++) bufA[k] = p[k * STRIDE_T];
        p += 8 * STRIDE_T;
        #pragma unroll
        for (int k = 0; k < 8; k++) STEP_F(bufB[k]);
        // last pair's bufB refill would read past the chunk (and past the array
        // on the final chunk) — clamp to a safe in-bounds address, data unused.
        const float* pb = (i < npair - 1) ? p : pfc + (b * NS + li);
        #pragma unroll
        for (int k = 0; k < 8; k++) bufB[k] = pb[k * STRIDE_T];
        p += 8 * STRIDE_T;
        #pragma unroll
        for (int k = 0; k < 8; k++) STEP_F(bufA[k]);
    }

    // ---- drain: flush remaining pipeline stages (8 iters, no pfc/loads) ----
    #pragma unroll
    for (int k = 0; k < 8; k++) STEP(0.0f, 0,1,1,1,1,1,1,1,1);

    #undef STEP_F
    #undef STEP

    const int cnt = acc_i - base_acc;   // payload-only PMC spike count
    if (li < 4) atomicAdd(&g_acc[b * NA + j], cnt);
}

__global__ void finalize_kernel(float* __restrict__ out, int out_size) {
    int b = blockIdx.x * blockDim.x + threadIdx.x;
    if (b >= BATCH) return;
    int c0 = g_acc[b * NA + 0];
    int c1 = g_acc[b * NA + 1];
    int c2 = g_acc[b * NA + 2];
    int c3 = g_acc[b * NA + 3];
    int best = 0, bv = c0;
    if (c1 > bv) { bv = c1; best = 1; }
    if (c2 > bv) { bv = c2; best = 2; }
    if (c3 > bv) { bv = c3; best = 3; }

    if (out_size == BATCH * (1 + NA)) {
        out[b] = (float)best;
        out[BATCH + b * NA + 0] = (float)c0;
        out[BATCH + b * NA + 1] = (float)c1;
        out[BATCH + b * NA + 2] = (float)c2;
        out[BATCH + b * NA + 3] = (float)c3;
    } else if (out_size == BATCH * NA) {
        out[b * NA + 0] = (float)c0;
        out[b * NA + 1] = (float)c1;
        out[b * NA + 2] = (float)c2;
        out[b * NA + 3] = (float)c3;
    } else if (out_size == BATCH) {
        ((int*)out)[b] = best;
    } else {
        if (b * NA + 3 < out_size) {
            out[b * NA + 0] = (float)c0;
            out[b * NA + 1] = (float)c1;
            out[b * NA + 2] = (float)c2;
            out[b * NA + 3] = (float)c3;
        }
        if (BATCH * NA + b < out_size) out[BATCH * NA + b] = (float)best;
    }
}

extern "C" void kernel_launch(void* const* d_in, const int* in_sizes, int n_in,
                              void* d_out, int out_size) {
    const float* pfc = (const float*)d_in[0];   // [2000, 1024, 16] f32
    const float* w1  = (const float*)d_in[1];   // [16, 4] f32
    const float* w2  = (const float*)d_in[2];   // [16, 4] f32

    zero_kernel<<<(BATCH * NA + 255) / 256, 256>>>();
    // 512 batch-pairs x 10 chunks = 5120 warps -> 1280 blocks of 4 warps
    bg_chunk_kernel<<<1280, 128>>>(pfc, w1, w2);
    finalize_kernel<<<(BATCH + 255) / 256, 256>>>((float*)d_out, out_size);
}

// round 5
// speedup vs baseline: 3.7862x; 1.5325x over previous
#include <cuda_runtime.h>
#include <stdint.h>

#define T_STEPS 2000
#define BATCH   1024
#define NS      16
#define NA      4
#define STRIDE_T (BATCH * NS)

#define C_CHUNKS 10
#define K_CHUNK  200     // payload timesteps per chunk (C*K = T)
#define HALO     48      // warm-up steps for chunks > 0

// per-(batch,chunk,action) payload PMC spike counts; every slot written each run
__device__ int g_part[BATCH * C_CHUNKS * NA];

// LIF step, bit-exact fp32 sequence (TAU == 1.0f in fp32):
//   v = v + (x - v); spike = (v >= 1); hard reset v = spike ? 0 : v
__device__ __forceinline__ bool lif_b(float& v, float x) {
    float dv = x - v;
    v = v + dv;
    bool fire = (v >= 1.0f);
    v = fire ? 0.0f : v;
    return fire;
}

__global__ __launch_bounds__(128, 9)
void bg_chunk_kernel(const float* __restrict__ pfc,
                     const float* __restrict__ w_pfc_d1,
                     const float* __restrict__ w_pfc_d2)
{
    __shared__ float2 lutA[256][NA];
    __shared__ float2 lutB[256][NA];

    const int tid = threadIdx.x;
    for (int e = tid; e < 512; e += blockDim.x) {
        const int hi = e >> 8;
        const int m  = e & 255;
        const int ibase = hi ? 8 : 0;
        #pragma unroll
        for (int jj = 0; jj < NA; jj++) {
            float a1 = 0.0f, a2 = 0.0f;
            #pragma unroll
            for (int i = 0; i < 8; i++)
                if ((m >> i) & 1) {
                    a1 += w_pfc_d1[(ibase + i) * NA + jj];
                    a2 += w_pfc_d2[(ibase + i) * NA + jj];
                }
            if (hi) lutB[m][jj] = make_float2(a1, a2);
            else    lutA[m][jj] = make_float2(a1, a2);
        }
    }
    __syncthreads();

    const int lane  = tid & 31;
    const int g     = blockIdx.x * 4 + (tid >> 5);  // global warp 0..5119
    const int pair  = g / C_CHUNKS;                 // batch pair 0..511
    const int chunk = g - pair * C_CHUNKS;          // 0..9
    const int grp   = lane >> 4;
    const int li    = lane & 15;
    const int b     = pair * 2 + grp;
    const int j     = lane & 3;
    const int shift = grp * 16;
    const unsigned full = 0xffffffffu;

    // pathway weights, exact reference fp32 op order
    const float w1j = (j == 0) ? 0.2f : (j == 1) ? 0.12f : (j == 2) ? 0.07f : 0.03f;
    const float w2j = (j == 0) ? 0.03f : (j == 1) ? 0.07f : (j == 2) ? 0.12f : 0.2f;
    const float W_D1_GPI   = (-1.0f * w1j) * 5.0f;
    const float W_D2_GPE   = (-1.0f * w1j) * 5.0f;
    const float W_GPE_STN  = (-0.8f * w1j) * 5.0f;
    const float W_STN_GPI  = (1.2f  * w1j) * 5.0f;
    const float W_GPI_THAL = (-1.0f * w2j) * 5.0f;
    const float W_THAL_PMC = (1.0f  * w1j) * 5.0f;

    // GPE..PMC are exactly stateless (each layer's sub-threshold current set has
    // <= 1 element, regenerated exactly; all supra-threshold currents fire from
    // any reachable v). So s_pmc(t) is a pure function of (s_d1(t), s_d2(t)):
    // build the 4-entry truth table with one exact LIF step per layer from v=0
    // (v' = x exactly, fire <=> x >= 1 -- identical to reference arithmetic).
    int tt = 0;
    #pragma unroll
    for (int cb = 0; cb < 4; cb++) {
        float sd1 = (cb & 2) ? 1.0f : 0.0f;
        float sd2 = (cb & 1) ? 1.0f : 0.0f;
        float xg = sd2 * W_D2_GPE + 1.5f;
        float sg = (xg >= 1.0f) ? 1.0f : 0.0f;
        float xs = sg * W_GPE_STN + 1.8f;
        float ss = (xs >= 1.0f) ? 1.0f : 0.0f;
        float xi = (sd1 * W_D1_GPI + ss * W_STN_GPI) + 1.5f;
        float si = (xi >= 1.0f) ? 1.0f : 0.0f;
        float xt = si * W_GPI_THAL + 1.2f;
        float st = (xt >= 1.0f) ? 1.0f : 0.0f;
        float xp = st * W_THAL_PMC + 0.5f;
        if (xp >= 1.0f) tt |= 1 << cb;
    }

    // chunk geometry
    const int t0    = chunk * K_CHUNK - (chunk ? HALO : 0);
    const int npair = chunk ? (HALO + K_CHUNK - 8) / 16 : (K_CHUNK - 8) / 16; // 15 / 12
    const int bsnap = chunk ? 2 : 1000;  // snapshot at pair 2, bufA-block, k==3

    float v_pfc = 0.0f, v_d1 = 0.0f, v_d2 = 0.0f;
    int acc_i = 0, base_acc = 0;

    // pipeline registers: PFC(t) | BAL(t-1) | LDS(t-2) | D12+count(t-3)
    bool s_pfc_b = false;
    unsigned m_reg = 0;
    float d1c = 0.0f, d2c = 0.0f;

    #define STEP(xv, EN_PFC, EN_BAL, EN_LDS, EN_D12)                      \
    {                                                                      \
        if (EN_D12) { bool a1 = lif_b(v_d1, d1c);                          \
                      bool a2 = lif_b(v_d2, d2c);                          \
                      int idx = (a1 ? 2 : 0) | (a2 ? 1 : 0);               \
                      acc_i += (tt >> idx) & 1; }                          \
        if (EN_LDS) { unsigned mlo = m_reg & 255u, mhi = m_reg >> 8;       \
                      float2 A  = lutA[mlo][j];                            \
                      float2 Bv = lutB[mhi][j];                            \
                      d1c = A.x + Bv.x;                                    \
                      d2c = A.y + Bv.y; }                                  \
        if (EN_BAL) { unsigned bal = __ballot_sync(full, s_pfc_b);         \
                      m_reg = (bal >> shift) & 0xFFFFu; }                  \
        if (EN_PFC) { s_pfc_b = lif_b(v_pfc, (xv)); }                      \
    }
    #define STEP_F(xv) STEP(xv, 1,1,1,1)

    const float* p = pfc + (size_t)t0 * STRIDE_T + b * NS + li;
    float bufA[8], bufB[8];

    #pragma unroll
    for (int k = 0; k < 8; k++) bufA[k] = p[k * STRIDE_T];
    p += 8 * STRIDE_T;
    #pragma unroll
    for (int k = 0; k < 8; k++) bufB[k] = p[k * STRIDE_T];
    p += 8 * STRIDE_T;

    // ---- pipeline fill: local t = 0..7 ----
    STEP(bufA[0], 1,0,0,0);
    STEP(bufA[1], 1,1,0,0);
    STEP(bufA[2], 1,1,1,0);
    STEP(bufA[3], 1,1,1,1);
    STEP(bufA[4], 1,1,1,1);
    STEP(bufA[5], 1,1,1,1);
    STEP(bufA[6], 1,1,1,1);
    STEP(bufA[7], 1,1,1,1);

    // ---- main: npair x 16 steps ----
    #pragma unroll 1
    for (int i = 0; i < npair; i++) {
        #pragma unroll
        for (int k = 0; k < 8; k++) bufA[k] = p[k * STRIDE_T];
        p += 8 * STRIDE_T;
        #pragma unroll
        for (int k = 0; k < 8; k++) STEP_F(bufB[k]);
        // last pair's refill would run past the chunk/array: clamp (data unused)
        const float* pb = (i < npair - 1) ? p : pfc + (b * NS + li);
        #pragma unroll
        for (int k = 0; k < 8; k++) bufB[k] = pb[k * STRIDE_T];
        p += 8 * STRIDE_T;
        #pragma unroll
        for (int k = 0; k < 8; k++) {
            // halo/payload boundary: pmc t=48 is counted at iter 51 =
            // pair 2, bufA block, k=3 -> snapshot just before that STEP
            if (k == 3) base_acc = (i == bsnap) ? acc_i : base_acc;
            STEP_F(bufA[k]);
        }
    }

    // ---- drain: flush remaining 3 pipeline stages ----
    STEP(0.0f, 0,1,1,1);
    STEP(0.0f, 0,0,1,1);
    STEP(0.0f, 0,0,0,1);

    #undef STEP_F
    #undef STEP

    if (li < 4) g_part[(b * C_CHUNKS + chunk) * NA + j] = acc_i - base_acc;
}

__global__ void finalize_kernel(float* __restrict__ out, int out_size) {
    int b = blockIdx.x * blockDim.x + threadIdx.x;
    if (b >= BATCH) return;
    int c[NA] = {0, 0, 0, 0};
    #pragma unroll
    for (int ch = 0; ch < C_CHUNKS; ch++) {
        const int* p = &g_part[(b * C_CHUNKS + ch) * NA];
        c[0] += p[0]; c[1] += p[1]; c[2] += p[2]; c[3] += p[3];
    }
    int best = 0, bv = c[0];
    if (c[1] > bv) { bv = c[1]; best = 1; }
    if (c[2] > bv) { bv = c[2]; best = 2; }
    if (c[3] > bv) { bv = c[3]; best = 3; }

    if (out_size == BATCH * (1 + NA)) {
        out[b] = (float)best;
        out[BATCH + b * NA + 0] = (float)c[0];
        out[BATCH + b * NA + 1] = (float)c[1];
        out[BATCH + b * NA + 2] = (float)c[2];
        out[BATCH + b * NA + 3] = (float)c[3];
    } else if (out_size == BATCH * NA) {
        out[b * NA + 0] = (float)c[0];
        out[b * NA + 1] = (float)c[1];
        out[b * NA + 2] = (float)c[2];
        out[b * NA + 3] = (float)c[3];
    } else if (out_size == BATCH) {
        ((int*)out)[b] = best;
    } else {
        if (b * NA + 3 < out_size) {
            out[b * NA + 0] = (float)c[0];
            out[b * NA + 1] = (float)c[1];
            out[b * NA + 2] = (float)c[2];
            out[b * NA + 3] = (float)c[3];
        }
        if (BATCH * NA + b < out_size) out[BATCH * NA + b] = (float)best;
    }
}

extern "C" void kernel_launch(void* const* d_in, const int* in_sizes, int n_in,
                              void* d_out, int out_size) {
    const float* pfc = (const float*)d_in[0];   // [2000, 1024, 16] f32
    const float* w1  = (const float*)d_in[1];   // [16, 4] f32
    const float* w2  = (const float*)d_in[2];   // [16, 4] f32

    // 512 batch-pairs x 10 chunks = 5120 warps -> 1280 blocks of 4 warps
    bg_chunk_kernel<<<1280, 128>>>(pfc, w1, w2);
    finalize_kernel<<<4, 256>>>((float*)d_out, out_size);
}

// round 6
// speedup vs baseline: 4.0973x; 1.0822x over previous
#include <cuda_runtime.h>
#include <stdint.h>

#define T_STEPS 2000
#define BATCH   1024
#define NS      16
#define NA      4
#define STRIDE_T (BATCH * NS)

#define C_CHUNKS 10
#define K_CHUNK  200     // payload timesteps per chunk (C*K = T)
#define HALO     48      // warm-up steps for chunks > 0 (6 groups of 8)

// per-(batch,chunk,action) payload PMC spike counts; every slot written each run
__device__ int g_part[BATCH * C_CHUNKS * NA];
__device__ int g_done = 0;   // block completion counter; reset by the finalizer

// LIF step, bit-exact fp32 sequence (TAU == 1.0f in fp32):
//   v = v + (x - v); spike = (v >= 1); hard reset v = spike ? 0 : v
__device__ __forceinline__ bool lif_b(float& v, float x) {
    float dv = x - v;
    v = v + dv;
    bool fire = (v >= 1.0f);
    v = fire ? 0.0f : v;
    return fire;
}

__global__ __launch_bounds__(128, 9)
void bg_kernel(const float* __restrict__ pfc,
               const float* __restrict__ w_pfc_d1,
               const float* __restrict__ w_pfc_d2,
               float* __restrict__ out, int out_size)
{
    __shared__ float2 lutA[256][NA];
    __shared__ float2 lutB[256][NA];
    __shared__ int s_last;

    const int tid = threadIdx.x;
    for (int e = tid; e < 512; e += blockDim.x) {
        const int hi = e >> 8;
        const int m  = e & 255;
        const int ibase = hi ? 8 : 0;
        #pragma unroll
        for (int jj = 0; jj < NA; jj++) {
            float a1 = 0.0f, a2 = 0.0f;
            #pragma unroll
            for (int i = 0; i < 8; i++)
                if ((m >> i) & 1) {
                    a1 += w_pfc_d1[(ibase + i) * NA + jj];
                    a2 += w_pfc_d2[(ibase + i) * NA + jj];
                }
            if (hi) lutB[m][jj] = make_float2(a1, a2);
            else    lutA[m][jj] = make_float2(a1, a2);
        }
    }
    __syncthreads();

    const int lane  = tid & 31;
    const int g     = blockIdx.x * 4 + (tid >> 5);  // global warp 0..5119
    const int pair  = g / C_CHUNKS;                 // batch pair 0..511
    const int chunk = g - pair * C_CHUNKS;          // 0..9
    const int grp   = lane >> 4;
    const int li    = lane & 15;
    const int b     = pair * 2 + grp;
    const int j     = lane & 3;
    const unsigned full = 0xffffffffu;
    // PRMT selectors: extract byte (2*grp) / (2*grp+1) of the ballot, zero-extend
    const unsigned sel_lo = 0x4440u | (unsigned)(grp * 2);
    const unsigned sel_hi = 0x4440u | (unsigned)(grp * 2 + 1);

    // pathway weights, exact reference fp32 op order
    const float w1j = (j == 0) ? 0.2f : (j == 1) ? 0.12f : (j == 2) ? 0.07f : 0.03f;
    const float w2j = (j == 0) ? 0.03f : (j == 1) ? 0.07f : (j == 2) ? 0.12f : 0.2f;
    const float W_D1_GPI   = (-1.0f * w1j) * 5.0f;
    const float W_D2_GPE   = (-1.0f * w1j) * 5.0f;
    const float W_GPE_STN  = (-0.8f * w1j) * 5.0f;
    const float W_STN_GPI  = (1.2f  * w1j) * 5.0f;
    const float W_GPI_THAL = (-1.0f * w2j) * 5.0f;
    const float W_THAL_PMC = (1.0f  * w1j) * 5.0f;

    // GPE..PMC are exactly stateless => s_pmc is a pure function of (s_d1, s_d2).
    // Build the 4-entry truth table with one exact LIF step per layer from v=0
    // (v' = x exactly, fire <=> x >= 1 -- identical to reference arithmetic).
    int tt = 0;
    #pragma unroll
    for (int cb = 0; cb < 4; cb++) {
        float sd1 = (cb & 2) ? 1.0f : 0.0f;
        float sd2 = (cb & 1) ? 1.0f : 0.0f;
        float xg = sd2 * W_D2_GPE + 1.5f;
        float sg = (xg >= 1.0f) ? 1.0f : 0.0f;
        float xs = sg * W_GPE_STN + 1.8f;
        float ss = (xs >= 1.0f) ? 1.0f : 0.0f;
        float xi = (sd1 * W_D1_GPI + ss * W_STN_GPI) + 1.5f;
        float si = (xi >= 1.0f) ? 1.0f : 0.0f;
        float xt = si * W_GPI_THAL + 1.2f;
        float st = (xt >= 1.0f) ? 1.0f : 0.0f;
        float xp = st * W_THAL_PMC + 0.5f;
        if (xp >= 1.0f) tt |= 1 << cb;
    }
    const int b0 = tt & 1, b1 = (tt >> 1) & 1, b2 = (tt >> 2) & 1, b3 = (tt >> 3) & 1;

    // chunk geometry: G groups of 8 steps; halo = first 6 groups for chunk > 0
    const int t0    = chunk * K_CHUNK - (chunk ? HALO : 0);
    const int npair = chunk ? 15 : 12;      // (G-1)/2, G = 31 or 25
    const int ihalo = chunk ? 2 : -1;       // zero acc after process(B) at i==2 (end of g5)

    float v_pfc = 0.0f, v_d1 = 0.0f, v_d2 = 0.0f;
    int acc_i = 0;

    #define STEP(xv)                                                       \
    {                                                                      \
        float dvp = (xv) - v_pfc;                                          \
        v_pfc = v_pfc + dvp;                                               \
        bool fp = (v_pfc >= 1.0f);                                         \
        v_pfc = fp ? 0.0f : v_pfc;                                         \
        unsigned bal = __ballot_sync(full, fp);                            \
        unsigned mlo = __byte_perm(bal, 0u, sel_lo);                       \
        unsigned mhi = __byte_perm(bal, 0u, sel_hi);                       \
        float2 A  = lutA[mlo][j];                                          \
        float2 Bv = lutB[mhi][j];                                          \
        float d1c = A.x + Bv.x;                                            \
        float d2c = A.y + Bv.y;                                            \
        bool p1 = lif_b(v_d1, d1c);                                        \
        bool p2 = lif_b(v_d2, d2c);                                        \
        acc_i += p1 ? (p2 ? b3 : b2) : (p2 ? b1 : b0);                     \
    }

    const float* p = pfc + (size_t)t0 * STRIDE_T + b * NS + li;
    float bufA[8], bufB[8];

    #pragma unroll
    for (int k = 0; k < 8; k++) bufA[k] = p[k * STRIDE_T];   // g0
    p += 8 * STRIDE_T;
    #pragma unroll
    for (int k = 0; k < 8; k++) bufB[k] = p[k * STRIDE_T];   // g1
    p += 8 * STRIDE_T;

    #pragma unroll
    for (int k = 0; k < 8; k++) STEP(bufA[k]);               // g0

    #pragma unroll 1
    for (int i = 0; i < npair; i++) {
        #pragma unroll
        for (int k = 0; k < 8; k++) bufA[k] = p[k * STRIDE_T];   // g(2i+2), always valid
        p += 8 * STRIDE_T;
        #pragma unroll
        for (int k = 0; k < 8; k++) STEP(bufB[k]);               // g(2i+1)
        if (i == ihalo) acc_i = 0;   // end of halo (g5 done), payload starts at g6
        // last iteration's B load (group G) is past the chunk/array: clamp (unused)
        const float* pb = (i < npair - 1) ? p : pfc + (b * NS + li);
        #pragma unroll
        for (int k = 0; k < 8; k++) bufB[k] = pb[k * STRIDE_T];  // g(2i+3)
        p += 8 * STRIDE_T;
        #pragma unroll
        for (int k = 0; k < 8; k++) STEP(bufA[k]);               // g(2i+2)
    }
    #undef STEP

    if (li < 4) g_part[(b * C_CHUNKS + chunk) * NA + j] = acc_i;

    // ---- last-block fused finalize ----
    __syncthreads();
    if (tid == 0) {
        __threadfence();
        int old = atomicAdd(&g_done, 1);
        s_last = (old == (int)gridDim.x - 1) ? 1 : 0;
    }
    __syncthreads();
    if (s_last) {
        __threadfence();   // acquire: all blocks' g_part writes are visible
        for (int bb = tid; bb < BATCH; bb += 128) {
            int c0 = 0, c1 = 0, c2 = 0, c3 = 0;
            #pragma unroll
            for (int ch = 0; ch < C_CHUNKS; ch++) {
                const int4 v4 = *(const int4*)&g_part[(bb * C_CHUNKS + ch) * NA];
                c0 += v4.x; c1 += v4.y; c2 += v4.z; c3 += v4.w;
            }
            int best = 0, bv = c0;
            if (c1 > bv) { bv = c1; best = 1; }
            if (c2 > bv) { bv = c2; best = 2; }
            if (c3 > bv) { bv = c3; best = 3; }

            if (out_size == BATCH * (1 + NA)) {
                out[bb] = (float)best;
                out[BATCH + bb * NA + 0] = (float)c0;
                out[BATCH + bb * NA + 1] = (float)c1;
                out[BATCH + bb * NA + 2] = (float)c2;
                out[BATCH + bb * NA + 3] = (float)c3;
            } else if (out_size == BATCH * NA) {
                out[bb * NA + 0] = (float)c0;
                out[bb * NA + 1] = (float)c1;
                out[bb * NA + 2] = (float)c2;
                out[bb * NA + 3] = (float)c3;
            } else if (out_size == BATCH) {
                ((int*)out)[bb] = best;
            } else {
                if (bb * NA + 3 < out_size) {
                    out[bb * NA + 0] = (float)c0;
                    out[bb * NA + 1] = (float)c1;
                    out[bb * NA + 2] = (float)c2;
                    out[bb * NA + 3] = (float)c3;
                }
                if (BATCH * NA + bb < out_size) out[BATCH * NA + bb] = (float)best;
            }
        }
        if (tid == 0) g_done = 0;   // reset for next graph replay
    }
}

extern "C" void kernel_launch(void* const* d_in, const int* in_sizes, int n_in,
                              void* d_out, int out_size) {
    const float* pfc = (const float*)d_in[0];   // [2000, 1024, 16] f32
    const float* w1  = (const float*)d_in[1];   // [16, 4] f32
    const float* w2  = (const float*)d_in[2];   // [16, 4] f32

    // 512 batch-pairs x 10 chunks = 5120 warps -> 1280 blocks of 4 warps
    bg_kernel<<<1280, 128>>>(pfc, w1, w2, (float*)d_out, out_size);
}

// round 7
// speedup vs baseline: 5.1223x; 1.2502x over previous
#include <cuda_runtime.h>
#include <stdint.h>

#define T_STEPS 2000
#define BATCH   1024
#define NS      16
#define NA      4
#define STRIDE_T (BATCH * NS)

#define C_CHUNKS 10
#define K_CHUNK  200     // payload timesteps per chunk (C*K = T)
#define HALO     48      // 6 groups of 8: 4 PFC-only + 2 full warm-up

// per-(batch,chunk,action) payload PMC spike counts; every slot written each run
__device__ int g_part[BATCH * C_CHUNKS * NA];
__device__ int g_done = 0;   // block completion counter; reset by the finalizer

__global__ __launch_bounds__(128, 5)
void bg_kernel(const float* __restrict__ pfc,
               const float* __restrict__ w_pfc_d1,
               const float* __restrict__ w_pfc_d2,
               float* __restrict__ out, int out_size)
{
    __shared__ float2 lutA[256][NA];
    __shared__ float2 lutB[256][NA];
    __shared__ int s_last;

    const int tid = threadIdx.x;
    for (int e = tid; e < 512; e += blockDim.x) {
        const int hi = e >> 8;
        const int m  = e & 255;
        const int ibase = hi ? 8 : 0;
        #pragma unroll
        for (int jj = 0; jj < NA; jj++) {
            float a1 = 0.0f, a2 = 0.0f;
            #pragma unroll
            for (int i = 0; i < 8; i++)
                if ((m >> i) & 1) {
                    a1 += w_pfc_d1[(ibase + i) * NA + jj];
                    a2 += w_pfc_d2[(ibase + i) * NA + jj];
                }
            if (hi) lutB[m][jj] = make_float2(a1, a2);
            else    lutA[m][jj] = make_float2(a1, a2);
        }
    }
    __syncthreads();

    const int lane  = tid & 31;
    const int w     = blockIdx.x * 4 + (tid >> 5);  // global warp 0..2559
    const int quad  = w / C_CHUNKS;                 // batch quad 0..255
    const int chunk = w - quad * C_CHUNKS;          // 0..9
    const int grp   = lane >> 3;                    // batch-within-warp 0..3
    const int pos   = lane & 7;                     // neuron index (also pos+8)
    const int b     = quad * 4 + grp;
    const int j     = pos & 3;
    const unsigned full = 0xffffffffu;
    // extract byte grp of a ballot, zero-extended
    const unsigned sel = 0x4440u | (unsigned)grp;

    // pathway weights, exact reference fp32 op order
    const float w1j = (j == 0) ? 0.2f : (j == 1) ? 0.12f : (j == 2) ? 0.07f : 0.03f;
    const float w2j = (j == 0) ? 0.03f : (j == 1) ? 0.07f : (j == 2) ? 0.12f : 0.2f;
    const float W_D1_GPI   = (-1.0f * w1j) * 5.0f;
    const float W_D2_GPE   = (-1.0f * w1j) * 5.0f;
    const float W_GPE_STN  = (-0.8f * w1j) * 5.0f;
    const float W_STN_GPI  = (1.2f  * w1j) * 5.0f;
    const float W_GPI_THAL = (-1.0f * w2j) * 5.0f;
    const float W_THAL_PMC = (1.0f  * w1j) * 5.0f;

    // GPE..PMC are exactly stateless => s_pmc is a pure function of (s_d1, s_d2).
    // 4-entry truth table via one exact LIF step per layer from v=0
    // (v' = x exactly, fire <=> x >= 1 -- identical to reference arithmetic).
    int tt = 0;
    #pragma unroll
    for (int cb = 0; cb < 4; cb++) {
        float sd1 = (cb & 2) ? 1.0f : 0.0f;
        float sd2 = (cb & 1) ? 1.0f : 0.0f;
        float xg = sd2 * W_D2_GPE + 1.5f;
        float sg = (xg >= 1.0f) ? 1.0f : 0.0f;
        float xs = sg * W_GPE_STN + 1.8f;
        float ss = (xs >= 1.0f) ? 1.0f : 0.0f;
        float xi = (sd1 * W_D1_GPI + ss * W_STN_GPI) + 1.5f;
        float si = (xi >= 1.0f) ? 1.0f : 0.0f;
        float xt = si * W_GPI_THAL + 1.2f;
        float st = (xt >= 1.0f) ? 1.0f : 0.0f;
        float xp = st * W_THAL_PMC + 0.5f;
        if (xp >= 1.0f) tt |= 1 << cb;
    }
    const int c00 = tt & 1, c01 = (tt >> 1) & 1, c10 = (tt >> 2) & 1, c11 = (tt >> 3) & 1;

    // chunk geometry: ngroups groups of 8 steps
    const int t0      = chunk * K_CHUNK - (chunk ? HALO : 0);
    const int ngroups = chunk ? 31 : 25;
    const int npair   = chunk ? 15 : 12;
    const int P       = chunk ? 4 : 0;   // first P groups: PFC-only warm-up
    const int R       = chunk ? 6 : 0;   // zero acc before this group (payload start)

    float v0 = 0.0f, v1 = 0.0f, vd1 = 0.0f, vd2 = 0.0f;
    int acc = 0;

    // full step: two PFC neurons -> 2 ballots -> LUT -> d1/d2 -> truth table
    #define STEP_FULL(xa, xb)                                              \
    {                                                                      \
        float dv0 = (xa) - v0; v0 = v0 + dv0;                              \
        bool f0 = (v0 >= 1.0f); v0 = f0 ? 0.0f : v0;                       \
        float dv1 = (xb) - v1; v1 = v1 + dv1;                              \
        bool f1 = (v1 >= 1.0f); v1 = f1 ? 0.0f : v1;                       \
        unsigned blo = __ballot_sync(full, f0);                            \
        unsigned bhi = __ballot_sync(full, f1);                            \
        unsigned mlo = __byte_perm(blo, 0u, sel);                          \
        unsigned mhi = __byte_perm(bhi, 0u, sel);                          \
        float2 A  = lutA[mlo][j];                                          \
        float2 Bv = lutB[mhi][j];                                          \
        float d1c = A.x + Bv.x;                                            \
        float d2c = A.y + Bv.y;                                            \
        float e1 = d1c - vd1; vd1 = vd1 + e1;                              \
        bool p1 = (vd1 >= 1.0f); vd1 = p1 ? 0.0f : vd1;                    \
        float e2 = d2c - vd2; vd2 = vd2 + e2;                              \
        bool p2 = (vd2 >= 1.0f); vd2 = p2 ? 0.0f : vd2;                    \
        acc += p1 ? (p2 ? c11 : c10) : (p2 ? c01 : c00);                   \
    }

    // PFC-only step (halo warm-up: only v0/v1 state matters this early)
    #define STEP_PFC(xa, xb)                                               \
    {                                                                      \
        float dv0 = (xa) - v0; v0 = v0 + dv0;                              \
        if (v0 >= 1.0f) v0 = 0.0f;                                         \
        float dv1 = (xb) - v1; v1 = v1 + dv1;                              \
        if (v1 >= 1.0f) v1 = 0.0f;                                         \
    }

    // process one 8-step group from buffer slot s, group index gi (warp-uniform)
    #define GROUP(s, gi)                                                   \
    {                                                                      \
        if ((gi) == R) acc = 0;                                            \
        if ((gi) < P) {                                                    \
            _Pragma("unroll")                                              \
            for (int k = 0; k < 8; k++) STEP_PFC(xa##s[k], xb##s[k]);      \
        } else {                                                           \
            _Pragma("unroll")                                              \
            for (int k = 0; k < 8; k++) STEP_FULL(xa##s[k], xb##s[k]);     \
        }                                                                  \
    }

    #define LOADG(s, ptr)                                                  \
    {                                                                      \
        _Pragma("unroll")                                                  \
        for (int k = 0; k < 8; k++) {                                      \
            xa##s[k] = (ptr)[k * STRIDE_T];                                \
            xb##s[k] = (ptr)[k * STRIDE_T + 8];                            \
        }                                                                  \
    }

    const float* p = pfc + (size_t)t0 * STRIDE_T + b * NS + pos;
    float xa0[8], xb0[8], xa1[8], xb1[8];

    LOADG(0, p); p += 8 * STRIDE_T;   // g0
    LOADG(1, p); p += 8 * STRIDE_T;   // g1

    GROUP(0, 0);                      // g0

    #pragma unroll 1
    for (int i = 0; i < npair; i++) {
        LOADG(0, p);                  // g(2i+2), always a valid group
        p += 8 * STRIDE_T;
        GROUP(1, 2 * i + 1);          // g(2i+1)
        // final iteration's refill (g(ngroups)) is past the chunk/array: clamp
        const float* pb = (i < npair - 1) ? p : pfc + (b * NS + pos);
        LOADG(1, pb);
        p += 8 * STRIDE_T;
        GROUP(0, 2 * i + 2);          // g(2i+2)
    }

    #undef LOADG
    #undef GROUP
    #undef STEP_PFC
    #undef STEP_FULL

    if (pos < 4) g_part[(b * C_CHUNKS + chunk) * NA + j] = acc;

    // ---- last-block fused finalize ----
    __syncthreads();
    if (tid == 0) {
        __threadfence();
        int old = atomicAdd(&g_done, 1);
        s_last = (old == (int)gridDim.x - 1) ? 1 : 0;
    }
    __syncthreads();
    if (s_last) {
        __threadfence();   // acquire: all blocks' g_part writes visible
        for (int bb = tid; bb < BATCH; bb += 128) {
            int c0 = 0, c1 = 0, c2 = 0, c3 = 0;
            #pragma unroll
            for (int ch = 0; ch < C_CHUNKS; ch++) {
                const int4 v4 = *(const int4*)&g_part[(bb * C_CHUNKS + ch) * NA];
                c0 += v4.x; c1 += v4.y; c2 += v4.z; c3 += v4.w;
            }
            int best = 0, bv = c0;
            if (c1 > bv) { bv = c1; best = 1; }
            if (c2 > bv) { bv = c2; best = 2; }
            if (c3 > bv) { bv = c3; best = 3; }

            if (out_size == BATCH * (1 + NA)) {
                out[bb] = (float)best;
                out[BATCH + bb * NA + 0] = (float)c0;
                out[BATCH + bb * NA + 1] = (float)c1;
                out[BATCH + bb * NA + 2] = (float)c2;
                out[BATCH + bb * NA + 3] = (float)c3;
            } else if (out_size == BATCH * NA) {
                out[bb * NA + 0] = (float)c0;
                out[bb * NA + 1] = (float)c1;
                out[bb * NA + 2] = (float)c2;
                out[bb * NA + 3] = (float)c3;
            } else if (out_size == BATCH) {
                ((int*)out)[bb] = best;
            } else {
                if (bb * NA + 3 < out_size) {
                    out[bb * NA + 0] = (float)c0;
                    out[bb * NA + 1] = (float)c1;
                    out[bb * NA + 2] = (float)c2;
                    out[bb * NA + 3] = (float)c3;
                }
                if (BATCH * NA + bb < out_size) out[BATCH * NA + bb] = (float)best;
            }
        }
        if (tid == 0) g_done = 0;   // reset for next graph replay
    }
}

extern "C" void kernel_launch(void* const* d_in, const int* in_sizes, int n_in,
                              void* d_out, int out_size) {
    const float* pfc = (const float*)d_in[0];   // [2000, 1024, 16] f32
    const float* w1  = (const float*)d_in[1];   // [16, 4] f32
    const float* w2  = (const float*)d_in[2];   // [16, 4] f32

    // 256 batch-quads x 10 chunks = 2560 warps -> 640 blocks of 4 warps
    bg_kernel<<<640, 128>>>(pfc, w1, w2, (float*)d_out, out_size);
}

// round 8
// speedup vs baseline: 5.1766x; 1.0106x over previous
#include <cuda_runtime.h>
#include <stdint.h>

#define T_STEPS 2000
#define BATCH   1024
#define NS      16
#define NA      4
#define STRIDE_T (BATCH * NS)

#define C_CHUNKS 10
#define K_CHUNK  200     // payload timesteps per chunk (C*K = T)
#define HALO     48      // 6 groups of 8: 4 PFC-only + 2 full warm-up

// per-(batch,chunk,action) payload PMC spike counts; every slot written each run
__device__ int g_part[BATCH * C_CHUNKS * NA];
__device__ int g_done = 0;   // block completion counter; reset by the finalizer

__global__ __launch_bounds__(128, 5)
void bg_kernel(const float* __restrict__ pfc,
               const float* __restrict__ w_pfc_d1,
               const float* __restrict__ w_pfc_d2,
               float* __restrict__ out, int out_size)
{
    __shared__ float2 lutA[256][NA];
    __shared__ float2 lutB[256][NA];
    __shared__ int s_last;

    const int tid = threadIdx.x;
    for (int e = tid; e < 512; e += blockDim.x) {
        const int hi = e >> 8;
        const int m  = e & 255;
        const int ibase = hi ? 8 : 0;
        #pragma unroll
        for (int jj = 0; jj < NA; jj++) {
            float a1 = 0.0f, a2 = 0.0f;
            #pragma unroll
            for (int i = 0; i < 8; i++)
                if ((m >> i) & 1) {
                    a1 += w_pfc_d1[(ibase + i) * NA + jj];
                    a2 += w_pfc_d2[(ibase + i) * NA + jj];
                }
            if (hi) lutB[m][jj] = make_float2(a1, a2);
            else    lutA[m][jj] = make_float2(a1, a2);
        }
    }
    __syncthreads();

    const int lane  = tid & 31;
    const int w     = blockIdx.x * 4 + (tid >> 5);  // global warp 0..2559
    const int quad  = w / C_CHUNKS;                 // batch quad 0..255
    const int chunk = w - quad * C_CHUNKS;          // 0..9
    const int grp   = lane >> 3;                    // batch-within-warp 0..3
    const int pos   = lane & 7;                     // neuron index (also pos+8)
    const int b     = quad * 4 + grp;
    const int j     = pos & 3;
    const unsigned full = 0xffffffffu;
    const unsigned sel = 0x4440u | (unsigned)grp;   // extract byte grp, zero-extend

    // pathway weights, exact reference fp32 op order
    const float w1j = (j == 0) ? 0.2f : (j == 1) ? 0.12f : (j == 2) ? 0.07f : 0.03f;
    const float w2j = (j == 0) ? 0.03f : (j == 1) ? 0.07f : (j == 2) ? 0.12f : 0.2f;
    const float W_D1_GPI   = (-1.0f * w1j) * 5.0f;
    const float W_D2_GPE   = (-1.0f * w1j) * 5.0f;
    const float W_GPE_STN  = (-0.8f * w1j) * 5.0f;
    const float W_STN_GPI  = (1.2f  * w1j) * 5.0f;
    const float W_GPI_THAL = (-1.0f * w2j) * 5.0f;
    const float W_THAL_PMC = (1.0f  * w1j) * 5.0f;

    // GPE..PMC exactly stateless => s_pmc = f(s_d1, s_d2); 4-entry truth table
    // built with one exact LIF step per layer from v=0 (v' = x exactly).
    int tt = 0;
    #pragma unroll
    for (int cb = 0; cb < 4; cb++) {
        float sd1 = (cb & 2) ? 1.0f : 0.0f;
        float sd2 = (cb & 1) ? 1.0f : 0.0f;
        float xg = sd2 * W_D2_GPE + 1.5f;
        float sg = (xg >= 1.0f) ? 1.0f : 0.0f;
        float xs = sg * W_GPE_STN + 1.8f;
        float ss = (xs >= 1.0f) ? 1.0f : 0.0f;
        float xi = (sd1 * W_D1_GPI + ss * W_STN_GPI) + 1.5f;
        float si = (xi >= 1.0f) ? 1.0f : 0.0f;
        float xt = si * W_GPI_THAL + 1.2f;
        float st = (xt >= 1.0f) ? 1.0f : 0.0f;
        float xp = st * W_THAL_PMC + 0.5f;
        if (xp >= 1.0f) tt |= 1 << cb;
    }
    const int c00 = tt & 1, c01 = (tt >> 1) & 1, c10 = (tt >> 2) & 1, c11 = (tt >> 3) & 1;

    // chunk geometry: ngroups groups of 8 steps
    const int t0    = chunk * K_CHUNK - (chunk ? HALO : 0);
    const int npair = chunk ? 15 : 12;   // (ngroups-1)/2, ngroups = 31 or 25
    const int P     = chunk ? 4 : 0;     // first P groups: PFC-only warm-up
    const int ZG    = chunk ? 6 : 0;     // zero acc before B of (group ZG, k==1)

    float v0 = 0.0f, v1 = 0.0f, vd1 = 0.0f, vd2 = 0.0f;
    int acc = 0;
    unsigned m_lo = 0, m_hi = 0;   // skew registers: ballots of the previous step

    // stage B: consume previous step's masks -> LUT -> d1/d2 LIF -> count
    #define STAGE_B()                                                      \
    {                                                                      \
        unsigned mlo = __byte_perm(m_lo, 0u, sel);                         \
        unsigned mhi = __byte_perm(m_hi, 0u, sel);                         \
        float2 A  = lutA[mlo][j];                                          \
        float2 Bv = lutB[mhi][j];                                          \
        float d1c = A.x + Bv.x;                                            \
        float d2c = A.y + Bv.y;                                            \
        float e1 = d1c - vd1; vd1 = vd1 + e1;                              \
        bool p1 = (vd1 >= 1.0f); vd1 = p1 ? 0.0f : vd1;                    \
        float e2 = d2c - vd2; vd2 = vd2 + e2;                              \
        bool p2 = (vd2 >= 1.0f); vd2 = p2 ? 0.0f : vd2;                    \
        acc += p1 ? (p2 ? c11 : c10) : (p2 ? c01 : c00);                   \
    }

    // stage A: two PFC neurons + ballots (produce this step's masks)
    #define STAGE_A(xa, xb)                                                \
    {                                                                      \
        float dv0 = (xa) - v0; v0 = v0 + dv0;                              \
        bool f0 = (v0 >= 1.0f); v0 = f0 ? 0.0f : v0;                       \
        float dv1 = (xb) - v1; v1 = v1 + dv1;                              \
        bool f1 = (v1 >= 1.0f); v1 = f1 ? 0.0f : v1;                       \
        m_lo = __ballot_sync(full, f0);                                    \
        m_hi = __ballot_sync(full, f1);                                    \
    }

    // PFC-only halo step (no ballot, no B; downstream state renews later)
    #define STEP_PFC(xa, xb)                                               \
    {                                                                      \
        float dv0 = (xa) - v0; v0 = v0 + dv0;                              \
        if (v0 >= 1.0f) v0 = 0.0f;                                         \
        float dv1 = (xb) - v1; v1 = v1 + dv1;                              \
        if (v1 >= 1.0f) v1 = 0.0f;                                         \
    }

    // one 8-step group from buffer slot s, group index gi (warp-uniform)
    #define GROUP(s, gi)                                                   \
    {                                                                      \
        if ((gi) < P) {                                                    \
            _Pragma("unroll")                                              \
            for (int k = 0; k < 8; k++) STEP_PFC(xa##s[k], xb##s[k]);      \
        } else {                                                           \
            _Pragma("unroll")                                              \
            for (int k = 0; k < 8; k++) {                                  \
                if (k == 1 && (gi) == ZG) acc = 0;                         \
                STAGE_B();                                                 \
                STAGE_A(xa##s[k], xb##s[k]);                               \
            }                                                              \
        }                                                                  \
    }

    #define LOADG(s, ptr)                                                  \
    {                                                                      \
        _Pragma("unroll")                                                  \
        for (int k = 0; k < 8; k++) {                                      \
            xa##s[k] = (ptr)[k * STRIDE_T];                                \
            xb##s[k] = (ptr)[k * STRIDE_T + 8];                            \
        }                                                                  \
    }

    const float* p = pfc + (size_t)t0 * STRIDE_T + b * NS + pos;
    float xa0[8], xb0[8], xa1[8], xb1[8];

    LOADG(0, p); p += 8 * STRIDE_T;   // g0
    LOADG(1, p); p += 8 * STRIDE_T;   // g1

    GROUP(0, 0);                      // g0

    #pragma unroll 1
    for (int i = 0; i < npair; i++) {
        LOADG(0, p);                  // g(2i+2), always a valid group
        p += 8 * STRIDE_T;
        GROUP(1, 2 * i + 1);          // g(2i+1)
        // final iteration's refill (past chunk/array): clamp, data unused
        const float* pb = (i < npair - 1) ? p : pfc + (b * NS + pos);
        LOADG(1, pb);
        p += 8 * STRIDE_T;
        GROUP(0, 2 * i + 2);          // g(2i+2)
    }

    STAGE_B();   // drain: count the final step

    #undef LOADG
    #undef GROUP
    #undef STEP_PFC
    #undef STAGE_A
    #undef STAGE_B

    if (pos < 4) g_part[(b * C_CHUNKS + chunk) * NA + j] = acc;

    // ---- last-block fused finalize ----
    __syncthreads();
    if (tid == 0) {
        __threadfence();
        int old = atomicAdd(&g_done, 1);
        s_last = (old == (int)gridDim.x - 1) ? 1 : 0;
    }
    __syncthreads();
    if (s_last) {
        __threadfence();   // acquire: all blocks' g_part writes visible
        for (int bb = tid; bb < BATCH; bb += 128) {
            int c0 = 0, c1 = 0, c2 = 0, c3 = 0;
            #pragma unroll
            for (int ch = 0; ch < C_CHUNKS; ch++) {
                const int4 v4 = *(const int4*)&g_part[(bb * C_CHUNKS + ch) * NA];
                c0 += v4.x; c1 += v4.y; c2 += v4.z; c3 += v4.w;
            }
            int best = 0, bv = c0;
            if (c1 > bv) { bv = c1; best = 1; }
            if (c2 > bv) { bv = c2; best = 2; }
            if (c3 > bv) { bv = c3; best = 3; }

            if (out_size == BATCH * (1 + NA)) {
                out[bb] = (float)best;
                out[BATCH + bb * NA + 0] = (float)c0;
                out[BATCH + bb * NA + 1] = (float)c1;
                out[BATCH + bb * NA + 2] = (float)c2;
                out[BATCH + bb * NA + 3] = (float)c3;
            } else if (out_size == BATCH * NA) {
                out[bb * NA + 0] = (float)c0;
                out[bb * NA + 1] = (float)c1;
                out[bb * NA + 2] = (float)c2;
                out[bb * NA + 3] = (float)c3;
            } else if (out_size == BATCH) {
                ((int*)out)[bb] = best;
            } else {
                if (bb * NA + 3 < out_size) {
                    out[bb * NA + 0] = (float)c0;
                    out[bb * NA + 1] = (float)c1;
                    out[bb * NA + 2] = (float)c2;
                    out[bb * NA + 3] = (float)c3;
                }
                if (BATCH * NA + bb < out_size) out[BATCH * NA + bb] = (float)best;
            }
        }
        if (tid == 0) g_done = 0;   // reset for next graph replay
    }
}

extern "C" void kernel_launch(void* const* d_in, const int* in_sizes, int n_in,
                              void* d_out, int out_size) {
    const float* pfc = (const float*)d_in[0];   // [2000, 1024, 16] f32
    const float* w1  = (const float*)d_in[1];   // [16, 4] f32
    const float* w2  = (const float*)d_in[2];   // [16, 4] f32

    // 256 batch-quads x 10 chunks = 2560 warps -> 640 blocks of 4 warps
    bg_kernel<<<640, 128>>>(pfc, w1, w2, (float*)d_out, out_size);
}